// round 9
// baseline (speedup 1.0000x reference)
#include <cuda_runtime.h>

// MultiLayerGRU fused: 3 stacked GRU layers, T=1024, B=4096, I=5, H0=15, H1=10, H2=2.
// Geometry: 148 blocks x 256 thr (8 warps) -> exactly one block per SM, 2
// warps per SMSP. Mixed load: warps 0-3 carry 4 batches (2 f32x2 pairs),
// warps 4-7 carry 3 batches (1 pair + 1 scalar batch). 28 batches/SM, even.
// Each SMSP gets one 4-batch and one 3-batch warp (wid%4 -> SMSP).
// Lane roles: 0..14 L0 units, 15..24 L1 units, 25..26 L2 units (store),
// 27..31 x loaders. Wavefront: step s computes h0(s), h1(s-1), h2(s-2).
// shfl source: src_k = (base+k) mod 32, base in {27,0,15}.
// Tail/overlap: base batch clamped; overlapping warps compute bit-identical
// values (same k-order, lo-lane arithmetic) so duplicate stores are benign.

#define T_STEPS 1024
#define BATCH   4096
#define IN_DIM  5

using u64 = unsigned long long;

__device__ __forceinline__ u64 pack2(float a, float b) {
    u64 r;
    asm("mov.b64 %0, {%1, %2};" : "=l"(r) : "f"(a), "f"(b));
    return r;
}
__device__ __forceinline__ void unpack2(u64 p, float& a, float& b) {
    asm("mov.b64 {%0, %1}, %2;" : "=f"(a), "=f"(b) : "l"(p));
}
__device__ __forceinline__ u64 fma2(u64 a, u64 b, u64 c) {
    u64 d;
    asm("fma.rn.f32x2 %0, %1, %2, %3;" : "=l"(d) : "l"(a), "l"(b), "l"(c));
    return d;
}

__device__ __forceinline__ float fsig(float a) {
    return __fdividef(1.0f, 1.0f + __expf(-a));
}
__device__ __forceinline__ float ftanh_(float v) {
    return 1.0f - 2.0f * __fdividef(1.0f, 1.0f + __expf(2.0f * v));
}

__global__ __launch_bounds__(256, 1)
void gru3_fused_kernel(
    const float* __restrict__ x,
    const float* __restrict__ w_ih0, const float* __restrict__ w_hh0,
    const float* __restrict__ b_ih0, const float* __restrict__ b_hh0,
    const float* __restrict__ w_ih1, const float* __restrict__ w_hh1,
    const float* __restrict__ b_ih1, const float* __restrict__ b_hh1,
    const float* __restrict__ w_ih2, const float* __restrict__ w_hh2,
    const float* __restrict__ b_ih2, const float* __restrict__ b_hh2,
    float* __restrict__ out)
{
    // ---- stage all weights into shared once ----
    __shared__ float sw[1884];
    {
        int t = threadIdx.x;
        for (int i = t; i < 225; i += 256) sw[i]        = w_ih0[i];
        for (int i = t; i < 675; i += 256) sw[225 + i]  = w_hh0[i];
        for (int i = t; i <  45; i += 256) sw[900 + i]  = b_ih0[i];
        for (int i = t; i <  45; i += 256) sw[945 + i]  = b_hh0[i];
        for (int i = t; i < 450; i += 256) sw[990 + i]  = w_ih1[i];
        for (int i = t; i < 300; i += 256) sw[1440 + i] = w_hh1[i];
        for (int i = t; i <  30; i += 256) sw[1740 + i] = b_ih1[i];
        for (int i = t; i <  30; i += 256) sw[1770 + i] = b_hh1[i];
        for (int i = t; i <  60; i += 256) sw[1800 + i] = w_ih2[i];
        for (int i = t; i <  12; i += 256) sw[1860 + i] = w_hh2[i];
        for (int i = t; i <   6; i += 256) sw[1872 + i] = b_ih2[i];
        for (int i = t; i <   6; i += 256) sw[1878 + i] = b_hh2[i];
    }
    __syncthreads();
    const float* s_wih0 = sw;
    const float* s_whh0 = sw + 225;
    const float* s_bih0 = sw + 900;
    const float* s_bhh0 = sw + 945;
    const float* s_wih1 = sw + 990;
    const float* s_whh1 = sw + 1440;
    const float* s_bih1 = sw + 1740;
    const float* s_bhh1 = sw + 1770;
    const float* s_wih2 = sw + 1800;
    const float* s_whh2 = sw + 1860;
    const float* s_bih2 = sw + 1872;
    const float* s_bhh2 = sw + 1878;

    const int lane = threadIdx.x & 31;
    const int wid  = threadIdx.x >> 5;          // 0..7
    const bool four = (wid < 4);                 // 4-batch vs 3-batch warp

    // base batch for this warp; 28 batches per block
    int bw = four ? (blockIdx.x * 28 + wid * 4)
                  : (blockIdx.x * 28 + 16 + (wid - 4) * 3);
    // clamp for tail (overlapping warps produce identical values)
    {
        int lim = four ? (BATCH - 4) : (BATCH - 3);
        if (bw > lim) bw = lim;
    }

    // ---- per-lane register-resident weights (unified k-loop, k = 0..24) ----
    float wr[25], wz[25], wni[15], wnh[20];
#pragma unroll
    for (int k = 0; k < 25; k++) { wr[k] = 0.f; wz[k] = 0.f; }
#pragma unroll
    for (int k = 0; k < 15; k++) wni[k] = 0.f;
#pragma unroll
    for (int k = 0; k < 20; k++) wnh[k] = 0.f;
    float br = 0.f, bz = 0.f, bni = 0.f, bnh = 0.f;

    if (lane < 15) {
        const int u = lane;
#pragma unroll
        for (int k = 0; k < 5; k++) {
            wr[k]  = s_wih0[u * 5 + k];
            wz[k]  = s_wih0[(15 + u) * 5 + k];
            wni[k] = s_wih0[(30 + u) * 5 + k];
        }
#pragma unroll
        for (int j = 0; j < 15; j++) {
            wr[5 + j]  = s_whh0[u * 15 + j];
            wz[5 + j]  = s_whh0[(15 + u) * 15 + j];
            wnh[j]     = s_whh0[(30 + u) * 15 + j];
        }
        br  = s_bih0[u] + s_bhh0[u];
        bz  = s_bih0[15 + u] + s_bhh0[15 + u];
        bni = s_bih0[30 + u];
        bnh = s_bhh0[30 + u];
    } else if (lane < 25) {
        const int u = lane - 15;
#pragma unroll
        for (int k = 0; k < 15; k++) {
            wr[k]  = s_wih1[u * 15 + k];
            wz[k]  = s_wih1[(10 + u) * 15 + k];
            wni[k] = s_wih1[(20 + u) * 15 + k];
        }
#pragma unroll
        for (int j = 0; j < 10; j++) {
            wr[15 + j]  = s_whh1[u * 10 + j];
            wz[15 + j]  = s_whh1[(10 + u) * 10 + j];
            wnh[10 + j] = s_whh1[(20 + u) * 10 + j];
        }
        br  = s_bih1[u] + s_bhh1[u];
        bz  = s_bih1[10 + u] + s_bhh1[10 + u];
        bni = s_bih1[20 + u];
        bnh = s_bhh1[20 + u];
    } else if (lane < 27) {
        const int u = lane - 25;
#pragma unroll
        for (int k = 0; k < 10; k++) {
            wr[k]  = s_wih2[u * 10 + k];
            wz[k]  = s_wih2[(2 + u) * 10 + k];
            wni[k] = s_wih2[(4 + u) * 10 + k];
        }
#pragma unroll
        for (int j = 0; j < 2; j++) {
            wr[10 + j] = s_whh2[u * 2 + j];
            wz[10 + j] = s_whh2[(2 + u) * 2 + j];
            wnh[5 + j] = s_whh2[(4 + u) * 2 + j];
        }
        br  = s_bih2[u] + s_bhh2[u];
        bz  = s_bih2[2 + u] + s_bhh2[2 + u];
        bni = s_bih2[4 + u];
        bnh = s_bhh2[4 + u];
    }

    // duplicate-packed weights (w,w) for f32x2 FMA — shared by all pairs
    u64 wr2[25], wz2[25], wni2[15], wnh2[20];
#pragma unroll
    for (int k = 0; k < 25; k++) { wr2[k] = pack2(wr[k], wr[k]); wz2[k] = pack2(wz[k], wz[k]); }
#pragma unroll
    for (int k = 0; k < 15; k++) wni2[k] = pack2(wni[k], wni[k]);
#pragma unroll
    for (int k = 0; k < 20; k++) wnh2[k] = pack2(wnh[k], wnh[k]);
    const u64 br2  = pack2(br, br);
    const u64 bz2  = pack2(bz, bz);
    const u64 bni2 = pack2(bni, bni);
    const u64 bnh2 = pack2(bnh, bnh);

    // shfl base per lane class: src_k = base + k (shfl wraps mod 32)
    const int base = (lane < 15) ? 27 : (lane < 25) ? 0 : 15;

    const bool isLoader = (lane >= 27);
    const bool isOut    = (lane == 25) || (lane == 26);
    const int d = (lane < 15) ? 0 : (lane < 25) ? 1 : (lane < 27) ? 2 : 0x40000000;

    const int feat = isLoader ? (lane - 27) : 0;
    const float* xp = x + (size_t)bw * IN_DIM + feat;
    const int u2 = (lane >= 25) ? (lane - 25) : 0;
    float* op = out + (size_t)bw * 2 + u2;

    if (four) {
        // ================= 4-batch warp: two packed pairs =================
        float h[4]  = {0.f, 0.f, 0.f, 0.f};
        float xn[4] = {0.f, 0.f, 0.f, 0.f};
        u64 sh0 = 0, sh1 = 0;
        if (isLoader) {
            sh0 = pack2(xp[0], xp[IN_DIM]);
            sh1 = pack2(xp[2 * IN_DIM], xp[3 * IN_DIM]);
#pragma unroll
            for (int j = 0; j < 4; j++) xn[j] = xp[BATCH * IN_DIM + j * IN_DIM];
        }

        for (int s = 0; s < T_STEPS + 2; ++s) {
            u64 ar0 = br2, az0 = bz2, ani0 = bni2, anh0 = bnh2;
            u64 ar1 = br2, az1 = bz2, ani1 = bni2, anh1 = bnh2;
#pragma unroll
            for (int k = 0; k < 25; k++) {
                u64 v0 = __shfl_sync(0xffffffffu, sh0, base + k);
                u64 v1 = __shfl_sync(0xffffffffu, sh1, base + k);
                ar0 = fma2(wr2[k], v0, ar0);
                ar1 = fma2(wr2[k], v1, ar1);
                az0 = fma2(wz2[k], v0, az0);
                az1 = fma2(wz2[k], v1, az1);
                if (k < 15) { ani0 = fma2(wni2[k], v0, ani0); ani1 = fma2(wni2[k], v1, ani1); }
                if (k >= 5) { anh0 = fma2(wnh2[k - 5], v0, anh0); anh1 = fma2(wnh2[k - 5], v1, anh1); }
            }

            float arf[4], azf[4], anif[4], anhf[4], hn[4];
            unpack2(ar0, arf[0], arf[1]);    unpack2(ar1, arf[2], arf[3]);
            unpack2(az0, azf[0], azf[1]);    unpack2(az1, azf[2], azf[3]);
            unpack2(ani0, anif[0], anif[1]); unpack2(ani1, anif[2], anif[3]);
            unpack2(anh0, anhf[0], anhf[1]); unpack2(anh1, anhf[2], anhf[3]);
#pragma unroll
            for (int j = 0; j < 4; j++) {
                float r = fsig(arf[j]);
                float z = fsig(azf[j]);
                float n = ftanh_(fmaf(r, anhf[j], anif[j]));
                hn[j] = fmaf(z, h[j] - n, n);
            }

            bool valid = (s >= d) && (s < T_STEPS + d);
            if (valid) {
#pragma unroll
                for (int j = 0; j < 4; j++) h[j] = hn[j];
            }
            if (valid && isOut) {
                size_t o = (size_t)(s - 2) * (BATCH * 2);
#pragma unroll
                for (int j = 0; j < 4; j++) op[o + j * 2] = hn[j];
            }

            if (isLoader) {
                sh0 = pack2(xn[0], xn[1]);
                sh1 = pack2(xn[2], xn[3]);
                int t2 = s + 2;
                bool inb = (t2 < T_STEPS);
                size_t xo = (size_t)t2 * (BATCH * IN_DIM);
#pragma unroll
                for (int j = 0; j < 4; j++) xn[j] = inb ? xp[xo + j * IN_DIM] : 0.f;
            } else {
                sh0 = pack2(h[0], h[1]);
                sh1 = pack2(h[2], h[3]);
            }
        }
    } else {
        // ========== 3-batch warp: one packed pair + one scalar batch ==========
        float h[3]  = {0.f, 0.f, 0.f};
        float xn[3] = {0.f, 0.f, 0.f};
        u64 sh0 = 0;
        float shS = 0.f;
        if (isLoader) {
            sh0 = pack2(xp[0], xp[IN_DIM]);
            shS = xp[2 * IN_DIM];
#pragma unroll
            for (int j = 0; j < 3; j++) xn[j] = xp[BATCH * IN_DIM + j * IN_DIM];
        }

        for (int s = 0; s < T_STEPS + 2; ++s) {
            u64 ar0 = br2, az0 = bz2, ani0 = bni2, anh0 = bnh2;
            u64 ar1 = br2, az1 = bz2, ani1 = bni2, anh1 = bnh2;
#pragma unroll
            for (int k = 0; k < 25; k++) {
                u64 v0 = __shfl_sync(0xffffffffu, sh0, base + k);
                float vs = __shfl_sync(0xffffffffu, shS, base + k);   // 1 shfl
                u64 v1 = pack2(vs, vs);                                // ALU, not MIO
                ar0 = fma2(wr2[k], v0, ar0);
                ar1 = fma2(wr2[k], v1, ar1);
                az0 = fma2(wz2[k], v0, az0);
                az1 = fma2(wz2[k], v1, az1);
                if (k < 15) { ani0 = fma2(wni2[k], v0, ani0); ani1 = fma2(wni2[k], v1, ani1); }
                if (k >= 5) { anh0 = fma2(wnh2[k - 5], v0, anh0); anh1 = fma2(wnh2[k - 5], v1, anh1); }
            }

            float arf[3], azf[3], anif[3], anhf[3], hn[3];
            float dummy;
            unpack2(ar0, arf[0], arf[1]);    unpack2(ar1, arf[2], dummy);
            unpack2(az0, azf[0], azf[1]);    unpack2(az1, azf[2], dummy);
            unpack2(ani0, anif[0], anif[1]); unpack2(ani1, anif[2], dummy);
            unpack2(anh0, anhf[0], anhf[1]); unpack2(anh1, anhf[2], dummy);
#pragma unroll
            for (int j = 0; j < 3; j++) {
                float r = fsig(arf[j]);
                float z = fsig(azf[j]);
                float n = ftanh_(fmaf(r, anhf[j], anif[j]));
                hn[j] = fmaf(z, h[j] - n, n);
            }

            bool valid = (s >= d) && (s < T_STEPS + d);
            if (valid) {
#pragma unroll
                for (int j = 0; j < 3; j++) h[j] = hn[j];
            }
            if (valid && isOut) {
                size_t o = (size_t)(s - 2) * (BATCH * 2);
#pragma unroll
                for (int j = 0; j < 3; j++) op[o + j * 2] = hn[j];
            }

            if (isLoader) {
                sh0 = pack2(xn[0], xn[1]);
                shS = xn[2];
                int t2 = s + 2;
                bool inb = (t2 < T_STEPS);
                size_t xo = (size_t)t2 * (BATCH * IN_DIM);
#pragma unroll
                for (int j = 0; j < 3; j++) xn[j] = inb ? xp[xo + j * IN_DIM] : 0.f;
            } else {
                sh0 = pack2(h[0], h[1]);
                shS = h[2];
            }
        }
    }
}

extern "C" void kernel_launch(void* const* d_in, const int* in_sizes, int n_in,
                              void* d_out, int out_size)
{
    (void)in_sizes; (void)n_in; (void)out_size;
    const float* x     = (const float*)d_in[0];
    const float* w_ih0 = (const float*)d_in[1];
    const float* w_hh0 = (const float*)d_in[2];
    const float* b_ih0 = (const float*)d_in[3];
    const float* b_hh0 = (const float*)d_in[4];
    const float* w_ih1 = (const float*)d_in[5];
    const float* w_hh1 = (const float*)d_in[6];
    const float* b_ih1 = (const float*)d_in[7];
    const float* b_hh1 = (const float*)d_in[8];
    const float* w_ih2 = (const float*)d_in[9];
    const float* w_hh2 = (const float*)d_in[10];
    const float* b_ih2 = (const float*)d_in[11];
    const float* b_hh2 = (const float*)d_in[12];

    // 148 blocks x 8 warps: one block per SM, 28 batches per SM,
    // each SMSP gets one 4-batch + one 3-batch warp.
    gru3_fused_kernel<<<148, 256>>>(
        x, w_ih0, w_hh0, b_ih0, b_hh0,
        w_ih1, w_hh1, b_ih1, b_hh1,
        w_ih2, w_hh2, b_ih2, b_hh2,
        (float*)d_out);
}

// round 10
// speedup vs baseline: 1.1335x; 1.1335x over previous
#include <cuda_runtime.h>

// MultiLayerGRU fused: 3 stacked GRU layers, T=1024, B=4096, I=5, H0=15, H1=10, H2=2.
// Structure identical to the proven R3 kernel (752us): one warp per FOUR batch
// elements (two independent f32x2 packed pairs per lane), 256 blocks x 128 thr.
// Lane roles:
//   lanes  0..14 : layer-0 units
//   lanes 15..24 : layer-1 units
//   lanes 25..26 : layer-2 units (write the output)
//   lanes 27..31 : x-feature loaders (prefetch x[t] into registers)
// Wavefront over layers: iteration s computes h0(s), h1(s-1), h2(s-2).
// shfl source: src_k = (base + k) mod 32, base in {27,0,15}.
//
// R10 change: r/z sigmoids via MUFU.TANH. sigma(a) = 0.5*tanh(a/2)+0.5, with
// the r/z weights and biases pre-scaled by 0.5 at pack time, so each sigmoid
// is tanh.approx.f32 + FFMA (2 inst, ~20cyc) instead of the ~5-inst ~44-cyc
// exp/rcp chain. The n-gate tanh stays exact (it feeds the recurrence value).

#define T_STEPS 1024
#define BATCH   4096
#define IN_DIM  5

using u64 = unsigned long long;

__device__ __forceinline__ u64 pack2(float a, float b) {
    u64 r;
    asm("mov.b64 %0, {%1, %2};" : "=l"(r) : "f"(a), "f"(b));
    return r;
}
__device__ __forceinline__ void unpack2(u64 p, float& a, float& b) {
    asm("mov.b64 {%0, %1}, %2;" : "=f"(a), "=f"(b) : "l"(p));
}
__device__ __forceinline__ u64 fma2(u64 a, u64 b, u64 c) {
    u64 d;
    asm("fma.rn.f32x2 %0, %1, %2, %3;" : "=l"(d) : "l"(a), "l"(b), "l"(c));
    return d;
}

__device__ __forceinline__ float tanh_ap(float a) {
    float r;
    asm("tanh.approx.f32 %0, %1;" : "=f"(r) : "f"(a));
    return r;
}
// exact tanh for the n gate: 1 - 2/(1+exp(2v))
__device__ __forceinline__ float ftanh_(float v) {
    return 1.0f - 2.0f * __fdividef(1.0f, 1.0f + __expf(2.0f * v));
}

__global__ __launch_bounds__(128, 2)
void gru3_fused_kernel(
    const float* __restrict__ x,
    const float* __restrict__ w_ih0, const float* __restrict__ w_hh0,
    const float* __restrict__ b_ih0, const float* __restrict__ b_hh0,
    const float* __restrict__ w_ih1, const float* __restrict__ w_hh1,
    const float* __restrict__ b_ih1, const float* __restrict__ b_hh1,
    const float* __restrict__ w_ih2, const float* __restrict__ w_hh2,
    const float* __restrict__ b_ih2, const float* __restrict__ b_hh2,
    float* __restrict__ out)
{
    // ---- stage all weights into shared once ----
    __shared__ float sw[1884];
    {
        int t = threadIdx.x;
        for (int i = t; i < 225; i += 128) sw[i]        = w_ih0[i];
        for (int i = t; i < 675; i += 128) sw[225 + i]  = w_hh0[i];
        for (int i = t; i <  45; i += 128) sw[900 + i]  = b_ih0[i];
        for (int i = t; i <  45; i += 128) sw[945 + i]  = b_hh0[i];
        for (int i = t; i < 450; i += 128) sw[990 + i]  = w_ih1[i];
        for (int i = t; i < 300; i += 128) sw[1440 + i] = w_hh1[i];
        for (int i = t; i <  30; i += 128) sw[1740 + i] = b_ih1[i];
        for (int i = t; i <  30; i += 128) sw[1770 + i] = b_hh1[i];
        for (int i = t; i <  60; i += 128) sw[1800 + i] = w_ih2[i];
        for (int i = t; i <  12; i += 128) sw[1860 + i] = w_hh2[i];
        for (int i = t; i <   6; i += 128) sw[1872 + i] = b_ih2[i];
        for (int i = t; i <   6; i += 128) sw[1878 + i] = b_hh2[i];
    }
    __syncthreads();
    const float* s_wih0 = sw;
    const float* s_whh0 = sw + 225;
    const float* s_bih0 = sw + 900;
    const float* s_bhh0 = sw + 945;
    const float* s_wih1 = sw + 990;
    const float* s_whh1 = sw + 1440;
    const float* s_bih1 = sw + 1740;
    const float* s_bhh1 = sw + 1770;
    const float* s_wih2 = sw + 1800;
    const float* s_whh2 = sw + 1860;
    const float* s_bih2 = sw + 1872;
    const float* s_bhh2 = sw + 1878;

    const int lane = threadIdx.x & 31;
    const int gw   = blockIdx.x * (blockDim.x >> 5) + (threadIdx.x >> 5);
    const int b0   = gw * 4;           // batches b0 .. b0+3

    // ---- per-lane register-resident weights (unified k-loop, k = 0..24) ----
    float wr[25], wz[25], wni[15], wnh[20];
#pragma unroll
    for (int k = 0; k < 25; k++) { wr[k] = 0.f; wz[k] = 0.f; }
#pragma unroll
    for (int k = 0; k < 15; k++) wni[k] = 0.f;
#pragma unroll
    for (int k = 0; k < 20; k++) wnh[k] = 0.f;
    float br = 0.f, bz = 0.f, bni = 0.f, bnh = 0.f;

    if (lane < 15) {
        const int u = lane;
#pragma unroll
        for (int k = 0; k < 5; k++) {
            wr[k]  = s_wih0[u * 5 + k];
            wz[k]  = s_wih0[(15 + u) * 5 + k];
            wni[k] = s_wih0[(30 + u) * 5 + k];
        }
#pragma unroll
        for (int j = 0; j < 15; j++) {
            wr[5 + j]  = s_whh0[u * 15 + j];
            wz[5 + j]  = s_whh0[(15 + u) * 15 + j];
            wnh[j]     = s_whh0[(30 + u) * 15 + j];
        }
        br  = s_bih0[u] + s_bhh0[u];
        bz  = s_bih0[15 + u] + s_bhh0[15 + u];
        bni = s_bih0[30 + u];
        bnh = s_bhh0[30 + u];
    } else if (lane < 25) {
        const int u = lane - 15;
#pragma unroll
        for (int k = 0; k < 15; k++) {
            wr[k]  = s_wih1[u * 15 + k];
            wz[k]  = s_wih1[(10 + u) * 15 + k];
            wni[k] = s_wih1[(20 + u) * 15 + k];
        }
#pragma unroll
        for (int j = 0; j < 10; j++) {
            wr[15 + j]  = s_whh1[u * 10 + j];
            wz[15 + j]  = s_whh1[(10 + u) * 10 + j];
            wnh[10 + j] = s_whh1[(20 + u) * 10 + j];
        }
        br  = s_bih1[u] + s_bhh1[u];
        bz  = s_bih1[10 + u] + s_bhh1[10 + u];
        bni = s_bih1[20 + u];
        bnh = s_bhh1[20 + u];
    } else if (lane < 27) {
        const int u = lane - 25;
#pragma unroll
        for (int k = 0; k < 10; k++) {
            wr[k]  = s_wih2[u * 10 + k];
            wz[k]  = s_wih2[(2 + u) * 10 + k];
            wni[k] = s_wih2[(4 + u) * 10 + k];
        }
#pragma unroll
        for (int j = 0; j < 2; j++) {
            wr[10 + j] = s_whh2[u * 2 + j];
            wz[10 + j] = s_whh2[(2 + u) * 2 + j];
            wnh[5 + j] = s_whh2[(4 + u) * 2 + j];
        }
        br  = s_bih2[u] + s_bhh2[u];
        bz  = s_bih2[2 + u] + s_bhh2[2 + u];
        bni = s_bih2[4 + u];
        bnh = s_bhh2[4 + u];
    }

    // duplicate-packed weights (w,w) for f32x2 FMA — shared by both batch pairs.
    // r/z weights and biases pre-scaled by 0.5: sigma(a)=0.5*tanh(a/2)+0.5.
    u64 wr2[25], wz2[25], wni2[15], wnh2[20];
#pragma unroll
    for (int k = 0; k < 25; k++) {
        float hr = 0.5f * wr[k], hz = 0.5f * wz[k];
        wr2[k] = pack2(hr, hr);
        wz2[k] = pack2(hz, hz);
    }
#pragma unroll
    for (int k = 0; k < 15; k++) wni2[k] = pack2(wni[k], wni[k]);
#pragma unroll
    for (int k = 0; k < 20; k++) wnh2[k] = pack2(wnh[k], wnh[k]);
    const u64 br2  = pack2(0.5f * br, 0.5f * br);
    const u64 bz2  = pack2(0.5f * bz, 0.5f * bz);
    const u64 bni2 = pack2(bni, bni);
    const u64 bnh2 = pack2(bnh, bnh);

    // shfl base per lane class: src_k = base + k (shfl wraps mod 32)
    const int base = (lane < 15) ? 27 : (lane < 25) ? 0 : 15;

    // wavefront delay per lane; loader lanes never commit
    const int d = (lane < 15) ? 0 : (lane < 25) ? 1 : (lane < 27) ? 2 : 0x40000000;
    const bool isOut = (lane == 25) || (lane == 26);

    // single base pointers; adjacent batches are immediate offsets
    const int feat = (lane >= 27) ? (lane - 27) : 0;
    const float* xp = x + (size_t)b0 * IN_DIM + feat;
    const int u2 = (lane >= 25) ? (lane - 25) : 0;
    float* op = out + (size_t)b0 * 2 + u2;

    float h[4] = {0.f, 0.f, 0.f, 0.f};   // hidden state, 4 batches
    float xn[4] = {0.f, 0.f, 0.f, 0.f};  // prefetched x(t+1)
    u64 sh0 = 0, sh1 = 0;                // packed shared operands
    if (lane >= 27) {
        sh0 = pack2(xp[0 * IN_DIM], xp[1 * IN_DIM]);             // x(0)
        sh1 = pack2(xp[2 * IN_DIM], xp[3 * IN_DIM]);
#pragma unroll
        for (int j = 0; j < 4; j++) xn[j] = xp[BATCH * IN_DIM + j * IN_DIM];  // x(1)
    }

    for (int s = 0; s < T_STEPS + 2; ++s) {
        u64 ar0 = br2, az0 = bz2, ani0 = bni2, anh0 = bnh2;
        u64 ar1 = br2, az1 = bz2, ani1 = bni2, anh1 = bnh2;
#pragma unroll
        for (int k = 0; k < 25; k++) {
            u64 v0 = __shfl_sync(0xffffffffu, sh0, base + k);    // wraps mod 32
            u64 v1 = __shfl_sync(0xffffffffu, sh1, base + k);
            ar0 = fma2(wr2[k], v0, ar0);
            ar1 = fma2(wr2[k], v1, ar1);
            az0 = fma2(wz2[k], v0, az0);
            az1 = fma2(wz2[k], v1, az1);
            if (k < 15) { ani0 = fma2(wni2[k], v0, ani0); ani1 = fma2(wni2[k], v1, ani1); }
            if (k >= 5) { anh0 = fma2(wnh2[k - 5], v0, anh0); anh1 = fma2(wnh2[k - 5], v1, anh1); }
        }

        float arf[4], azf[4], anif[4], anhf[4], hn[4];
        unpack2(ar0, arf[0], arf[1]);    unpack2(ar1, arf[2], arf[3]);
        unpack2(az0, azf[0], azf[1]);    unpack2(az1, azf[2], azf[3]);
        unpack2(ani0, anif[0], anif[1]); unpack2(ani1, anif[2], anif[3]);
        unpack2(anh0, anhf[0], anhf[1]); unpack2(anh1, anhf[2], anhf[3]);
#pragma unroll
        for (int j = 0; j < 4; j++) {
            // arf/azf are pre-scaled by 0.5: sigma = 0.5*tanh + 0.5
            float r = fmaf(tanh_ap(arf[j]), 0.5f, 0.5f);
            float z = fmaf(tanh_ap(azf[j]), 0.5f, 0.5f);
            float n = ftanh_(fmaf(r, anhf[j], anif[j]));         // exact tanh
            hn[j] = fmaf(z, h[j] - n, n);                        // (1-z)*n + z*h
        }

        bool valid = (s >= d) && (s < T_STEPS + d);
        if (valid) {
#pragma unroll
            for (int j = 0; j < 4; j++) h[j] = hn[j];
        }
        if (valid && isOut) {
            size_t o = (size_t)(s - 2) * (BATCH * 2);
#pragma unroll
            for (int j = 0; j < 4; j++) op[o + j * 2] = hn[j];
        }

        if (lane < 27) {
            sh0 = pack2(h[0], h[1]);
            sh1 = pack2(h[2], h[3]);
        } else {
            sh0 = pack2(xn[0], xn[1]);                           // becomes x(s+1)
            sh1 = pack2(xn[2], xn[3]);
            int t2 = s + 2;
            bool inb = (t2 < T_STEPS);
            size_t xo = (size_t)t2 * (BATCH * IN_DIM);
#pragma unroll
            for (int j = 0; j < 4; j++) xn[j] = inb ? xp[xo + j * IN_DIM] : 0.f;
        }
    }
}

extern "C" void kernel_launch(void* const* d_in, const int* in_sizes, int n_in,
                              void* d_out, int out_size)
{
    (void)in_sizes; (void)n_in; (void)out_size;
    const float* x     = (const float*)d_in[0];
    const float* w_ih0 = (const float*)d_in[1];
    const float* w_hh0 = (const float*)d_in[2];
    const float* b_ih0 = (const float*)d_in[3];
    const float* b_hh0 = (const float*)d_in[4];
    const float* w_ih1 = (const float*)d_in[5];
    const float* w_hh1 = (const float*)d_in[6];
    const float* b_ih1 = (const float*)d_in[7];
    const float* b_hh1 = (const float*)d_in[8];
    const float* w_ih2 = (const float*)d_in[9];
    const float* w_hh2 = (const float*)d_in[10];
    const float* b_ih2 = (const float*)d_in[11];
    const float* b_hh2 = (const float*)d_in[12];

    // one warp per 4 batch elements: 1024 warps = 256 blocks x 4 warps
    gru3_fused_kernel<<<BATCH / 16, 128>>>(
        x, w_ih0, w_hh0, b_ih0, b_hh0,
        w_ih1, w_hh1, b_ih1, b_hh1,
        w_ih2, w_hh2, b_ih2, b_hh2,
        (float*)d_out);
}

// round 11
// speedup vs baseline: 1.6407x; 1.4474x over previous
#include <cuda_runtime.h>

// MultiLayerGRU fused: 3 stacked GRU layers, T=1024, B=4096, I=5, H0=15, H1=10, H2=2.
// Hot loop identical to the proven R3 kernel (752us): one warp per FOUR batch
// elements, two independent f32x2 packed pairs per lane, duplicated (w,w)
// register-resident weights, exact exp/rcp activations.
// R11 change is GEOMETRY ONLY: 148 blocks x 224 thr (7 warps) -> one block
// per SM, 28 batches/SM on every SM (R3 had 32 on 108 SMs / 16 on 40 SMs).
// SMSP distribution per block is (2,2,2,1) - no SMSP exceeds R3's 2 warps.
// 1036 warps cover 4096 batches; the 12 surplus warps clamp to batches
// 4092..4095 and recompute them bit-identically (duplicate stores benign).
// Lane roles:
//   lanes  0..14 : layer-0 units
//   lanes 15..24 : layer-1 units
//   lanes 25..26 : layer-2 units (write the output)
//   lanes 27..31 : x-feature loaders (prefetch x[t] into registers)
// Wavefront over layers: iteration s computes h0(s), h1(s-1), h2(s-2).
// shfl source: src_k = (base + k) mod 32, base in {27,0,15}.

#define T_STEPS 1024
#define BATCH   4096
#define IN_DIM  5

using u64 = unsigned long long;

__device__ __forceinline__ u64 pack2(float a, float b) {
    u64 r;
    asm("mov.b64 %0, {%1, %2};" : "=l"(r) : "f"(a), "f"(b));
    return r;
}
__device__ __forceinline__ void unpack2(u64 p, float& a, float& b) {
    asm("mov.b64 {%0, %1}, %2;" : "=f"(a), "=f"(b) : "l"(p));
}
__device__ __forceinline__ u64 fma2(u64 a, u64 b, u64 c) {
    u64 d;
    asm("fma.rn.f32x2 %0, %1, %2, %3;" : "=l"(d) : "l"(a), "l"(b), "l"(c));
    return d;
}

__device__ __forceinline__ float fsig(float a) {
    return __fdividef(1.0f, 1.0f + __expf(-a));
}
__device__ __forceinline__ float ftanh_(float v) {
    return 1.0f - 2.0f * __fdividef(1.0f, 1.0f + __expf(2.0f * v));
}

__global__ __launch_bounds__(224, 1)
void gru3_fused_kernel(
    const float* __restrict__ x,
    const float* __restrict__ w_ih0, const float* __restrict__ w_hh0,
    const float* __restrict__ b_ih0, const float* __restrict__ b_hh0,
    const float* __restrict__ w_ih1, const float* __restrict__ w_hh1,
    const float* __restrict__ b_ih1, const float* __restrict__ b_hh1,
    const float* __restrict__ w_ih2, const float* __restrict__ w_hh2,
    const float* __restrict__ b_ih2, const float* __restrict__ b_hh2,
    float* __restrict__ out)
{
    // ---- stage all weights into shared once ----
    __shared__ float sw[1884];
    {
        int t = threadIdx.x;
        for (int i = t; i < 225; i += 224) sw[i]        = w_ih0[i];
        for (int i = t; i < 675; i += 224) sw[225 + i]  = w_hh0[i];
        for (int i = t; i <  45; i += 224) sw[900 + i]  = b_ih0[i];
        for (int i = t; i <  45; i += 224) sw[945 + i]  = b_hh0[i];
        for (int i = t; i < 450; i += 224) sw[990 + i]  = w_ih1[i];
        for (int i = t; i < 300; i += 224) sw[1440 + i] = w_hh1[i];
        for (int i = t; i <  30; i += 224) sw[1740 + i] = b_ih1[i];
        for (int i = t; i <  30; i += 224) sw[1770 + i] = b_hh1[i];
        for (int i = t; i <  60; i += 224) sw[1800 + i] = w_ih2[i];
        for (int i = t; i <  12; i += 224) sw[1860 + i] = w_hh2[i];
        for (int i = t; i <   6; i += 224) sw[1872 + i] = b_ih2[i];
        for (int i = t; i <   6; i += 224) sw[1878 + i] = b_hh2[i];
    }
    __syncthreads();
    const float* s_wih0 = sw;
    const float* s_whh0 = sw + 225;
    const float* s_bih0 = sw + 900;
    const float* s_bhh0 = sw + 945;
    const float* s_wih1 = sw + 990;
    const float* s_whh1 = sw + 1440;
    const float* s_bih1 = sw + 1740;
    const float* s_bhh1 = sw + 1770;
    const float* s_wih2 = sw + 1800;
    const float* s_whh2 = sw + 1860;
    const float* s_bih2 = sw + 1872;
    const float* s_bhh2 = sw + 1878;

    const int lane = threadIdx.x & 31;
    const int gw   = blockIdx.x * (blockDim.x >> 5) + (threadIdx.x >> 5);
    int b0 = gw * 4;                     // batches b0 .. b0+3
    if (b0 > BATCH - 4) b0 = BATCH - 4;  // surplus warps: bit-identical recompute

    // ---- per-lane register-resident weights (unified k-loop, k = 0..24) ----
    float wr[25], wz[25], wni[15], wnh[20];
#pragma unroll
    for (int k = 0; k < 25; k++) { wr[k] = 0.f; wz[k] = 0.f; }
#pragma unroll
    for (int k = 0; k < 15; k++) wni[k] = 0.f;
#pragma unroll
    for (int k = 0; k < 20; k++) wnh[k] = 0.f;
    float br = 0.f, bz = 0.f, bni = 0.f, bnh = 0.f;

    if (lane < 15) {
        const int u = lane;
#pragma unroll
        for (int k = 0; k < 5; k++) {
            wr[k]  = s_wih0[u * 5 + k];
            wz[k]  = s_wih0[(15 + u) * 5 + k];
            wni[k] = s_wih0[(30 + u) * 5 + k];
        }
#pragma unroll
        for (int j = 0; j < 15; j++) {
            wr[5 + j]  = s_whh0[u * 15 + j];
            wz[5 + j]  = s_whh0[(15 + u) * 15 + j];
            wnh[j]     = s_whh0[(30 + u) * 15 + j];
        }
        br  = s_bih0[u] + s_bhh0[u];
        bz  = s_bih0[15 + u] + s_bhh0[15 + u];
        bni = s_bih0[30 + u];
        bnh = s_bhh0[30 + u];
    } else if (lane < 25) {
        const int u = lane - 15;
#pragma unroll
        for (int k = 0; k < 15; k++) {
            wr[k]  = s_wih1[u * 15 + k];
            wz[k]  = s_wih1[(10 + u) * 15 + k];
            wni[k] = s_wih1[(20 + u) * 15 + k];
        }
#pragma unroll
        for (int j = 0; j < 10; j++) {
            wr[15 + j]  = s_whh1[u * 10 + j];
            wz[15 + j]  = s_whh1[(10 + u) * 10 + j];
            wnh[10 + j] = s_whh1[(20 + u) * 10 + j];
        }
        br  = s_bih1[u] + s_bhh1[u];
        bz  = s_bih1[10 + u] + s_bhh1[10 + u];
        bni = s_bih1[20 + u];
        bnh = s_bhh1[20 + u];
    } else if (lane < 27) {
        const int u = lane - 25;
#pragma unroll
        for (int k = 0; k < 10; k++) {
            wr[k]  = s_wih2[u * 10 + k];
            wz[k]  = s_wih2[(2 + u) * 10 + k];
            wni[k] = s_wih2[(4 + u) * 10 + k];
        }
#pragma unroll
        for (int j = 0; j < 2; j++) {
            wr[10 + j] = s_whh2[u * 2 + j];
            wz[10 + j] = s_whh2[(2 + u) * 2 + j];
            wnh[5 + j] = s_whh2[(4 + u) * 2 + j];
        }
        br  = s_bih2[u] + s_bhh2[u];
        bz  = s_bih2[2 + u] + s_bhh2[2 + u];
        bni = s_bih2[4 + u];
        bnh = s_bhh2[4 + u];
    }

    // duplicate-packed weights (w,w) for f32x2 FMA — shared by both batch pairs
    u64 wr2[25], wz2[25], wni2[15], wnh2[20];
#pragma unroll
    for (int k = 0; k < 25; k++) { wr2[k] = pack2(wr[k], wr[k]); wz2[k] = pack2(wz[k], wz[k]); }
#pragma unroll
    for (int k = 0; k < 15; k++) wni2[k] = pack2(wni[k], wni[k]);
#pragma unroll
    for (int k = 0; k < 20; k++) wnh2[k] = pack2(wnh[k], wnh[k]);
    const u64 br2  = pack2(br, br);
    const u64 bz2  = pack2(bz, bz);
    const u64 bni2 = pack2(bni, bni);
    const u64 bnh2 = pack2(bnh, bnh);

    // shfl base per lane class: src_k = base + k (shfl wraps mod 32)
    const int base = (lane < 15) ? 27 : (lane < 25) ? 0 : 15;

    // wavefront delay per lane; loader lanes never commit
    const int d = (lane < 15) ? 0 : (lane < 25) ? 1 : (lane < 27) ? 2 : 0x40000000;
    const bool isOut = (lane == 25) || (lane == 26);

    // single base pointers; adjacent batches are immediate offsets
    const int feat = (lane >= 27) ? (lane - 27) : 0;
    const float* xp = x + (size_t)b0 * IN_DIM + feat;
    const int u2 = (lane >= 25) ? (lane - 25) : 0;
    float* op = out + (size_t)b0 * 2 + u2;

    float h[4] = {0.f, 0.f, 0.f, 0.f};   // hidden state, 4 batches
    float xn[4] = {0.f, 0.f, 0.f, 0.f};  // prefetched x(t+1)
    u64 sh0 = 0, sh1 = 0;                // packed shared operands
    if (lane >= 27) {
        sh0 = pack2(xp[0 * IN_DIM], xp[1 * IN_DIM]);             // x(0)
        sh1 = pack2(xp[2 * IN_DIM], xp[3 * IN_DIM]);
#pragma unroll
        for (int j = 0; j < 4; j++) xn[j] = xp[BATCH * IN_DIM + j * IN_DIM];  // x(1)
    }

    for (int s = 0; s < T_STEPS + 2; ++s) {
        u64 ar0 = br2, az0 = bz2, ani0 = bni2, anh0 = bnh2;
        u64 ar1 = br2, az1 = bz2, ani1 = bni2, anh1 = bnh2;
#pragma unroll
        for (int k = 0; k < 25; k++) {
            u64 v0 = __shfl_sync(0xffffffffu, sh0, base + k);    // wraps mod 32
            u64 v1 = __shfl_sync(0xffffffffu, sh1, base + k);
            ar0 = fma2(wr2[k], v0, ar0);
            ar1 = fma2(wr2[k], v1, ar1);
            az0 = fma2(wz2[k], v0, az0);
            az1 = fma2(wz2[k], v1, az1);
            if (k < 15) { ani0 = fma2(wni2[k], v0, ani0); ani1 = fma2(wni2[k], v1, ani1); }
            if (k >= 5) { anh0 = fma2(wnh2[k - 5], v0, anh0); anh1 = fma2(wnh2[k - 5], v1, anh1); }
        }

        float arf[4], azf[4], anif[4], anhf[4], hn[4];
        unpack2(ar0, arf[0], arf[1]);    unpack2(ar1, arf[2], arf[3]);
        unpack2(az0, azf[0], azf[1]);    unpack2(az1, azf[2], azf[3]);
        unpack2(ani0, anif[0], anif[1]); unpack2(ani1, anif[2], anif[3]);
        unpack2(anh0, anhf[0], anhf[1]); unpack2(anh1, anhf[2], anhf[3]);
#pragma unroll
        for (int j = 0; j < 4; j++) {
            float r = fsig(arf[j]);
            float z = fsig(azf[j]);
            float n = ftanh_(fmaf(r, anhf[j], anif[j]));
            hn[j] = fmaf(z, h[j] - n, n);                        // (1-z)*n + z*h
        }

        bool valid = (s >= d) && (s < T_STEPS + d);
        if (valid) {
#pragma unroll
            for (int j = 0; j < 4; j++) h[j] = hn[j];
        }
        if (valid && isOut) {
            size_t o = (size_t)(s - 2) * (BATCH * 2);
#pragma unroll
            for (int j = 0; j < 4; j++) op[o + j * 2] = hn[j];
        }

        if (lane < 27) {
            sh0 = pack2(h[0], h[1]);
            sh1 = pack2(h[2], h[3]);
        } else {
            sh0 = pack2(xn[0], xn[1]);                           // becomes x(s+1)
            sh1 = pack2(xn[2], xn[3]);
            int t2 = s + 2;
            bool inb = (t2 < T_STEPS);
            size_t xo = (size_t)t2 * (BATCH * IN_DIM);
#pragma unroll
            for (int j = 0; j < 4; j++) xn[j] = inb ? xp[xo + j * IN_DIM] : 0.f;
        }
    }
}

extern "C" void kernel_launch(void* const* d_in, const int* in_sizes, int n_in,
                              void* d_out, int out_size)
{
    (void)in_sizes; (void)n_in; (void)out_size;
    const float* x     = (const float*)d_in[0];
    const float* w_ih0 = (const float*)d_in[1];
    const float* w_hh0 = (const float*)d_in[2];
    const float* b_ih0 = (const float*)d_in[3];
    const float* b_hh0 = (const float*)d_in[4];
    const float* w_ih1 = (const float*)d_in[5];
    const float* w_hh1 = (const float*)d_in[6];
    const float* b_ih1 = (const float*)d_in[7];
    const float* b_hh1 = (const float*)d_in[8];
    const float* w_ih2 = (const float*)d_in[9];
    const float* w_hh2 = (const float*)d_in[10];
    const float* b_ih2 = (const float*)d_in[11];
    const float* b_hh2 = (const float*)d_in[12];

    // 148 blocks x 7 warps = 1036 warps (uniform 4-batch bodies),
    // one block per SM, 28 batches per SM on every SM.
    gru3_fused_kernel<<<148, 224>>>(
        x, w_ih0, w_hh0, b_ih0, b_hh0,
        w_ih1, w_hh1, b_ih1, b_hh1,
        w_ih2, w_hh2, b_ih2, b_hh2,
        (float*)d_out);
}

// round 12
// speedup vs baseline: 1.8128x; 1.1049x over previous
#include <cuda_runtime.h>

// MultiLayerGRU fused: 3 stacked GRU layers, T=1024, B=4096, I=5, H0=15, H1=10, H2=2.
// R3 core (one warp per FOUR batches, two f32x2 packed pairs, duplicated (w,w)
// register weights, exact activations) and R3 geometry (256 blocks x 128 thr,
// 4 warps -> proper SMSP spread). R12 change: operand distribution via a
// per-warp double-buffered SMEM float4 broadcast instead of shuffles:
// each lane stores its packed 4-batch operand at [lane] and [lane+32] (wrap
// duplicate), then reads 25 consecutive float4s [base+k] with ld.shared.v4
// at immediate offsets. 25 LDS.128 + 2 STS.128 + 1 syncwarp replace 100
// SHFL.b32 per step (~75 fewer issue slots). NOTE: R4 tested this body with
// 32-thread blocks, which piles every CTA's single warp onto SMSP0 (wid%4) -
// that measurement was invalid; this is the first fair test.
// Lane roles:
//   lanes  0..14 : layer-0 units     (read slots 27..51)
//   lanes 15..24 : layer-1 units     (read slots  0..24)
//   lanes 25..26 : layer-2 units     (read slots 15..39; store output)
//   lanes 27..31 : x loaders         (publish x; reads unused, weights 0)
// Wavefront: step s computes h0(s), h1(s-1), h2(s-2).

#define T_STEPS 1024
#define BATCH   4096
#define IN_DIM  5

using u64 = unsigned long long;

__device__ __forceinline__ u64 pack2(float a, float b) {
    u64 r;
    asm("mov.b64 %0, {%1, %2};" : "=l"(r) : "f"(a), "f"(b));
    return r;
}
__device__ __forceinline__ void unpack2(u64 p, float& a, float& b) {
    asm("mov.b64 {%0, %1}, %2;" : "=f"(a), "=f"(b) : "l"(p));
}
__device__ __forceinline__ u64 fma2(u64 a, u64 b, u64 c) {
    u64 d;
    asm("fma.rn.f32x2 %0, %1, %2, %3;" : "=l"(d) : "l"(a), "l"(b), "l"(c));
    return d;
}

__device__ __forceinline__ float fsig(float a) {
    return __fdividef(1.0f, 1.0f + __expf(-a));
}
__device__ __forceinline__ float ftanh_(float v) {
    return 1.0f - 2.0f * __fdividef(1.0f, 1.0f + __expf(2.0f * v));
}

__global__ __launch_bounds__(128, 2)
void gru3_fused_kernel(
    const float* __restrict__ x,
    const float* __restrict__ w_ih0, const float* __restrict__ w_hh0,
    const float* __restrict__ b_ih0, const float* __restrict__ b_hh0,
    const float* __restrict__ w_ih1, const float* __restrict__ w_hh1,
    const float* __restrict__ b_ih1, const float* __restrict__ b_hh1,
    const float* __restrict__ w_ih2, const float* __restrict__ w_hh2,
    const float* __restrict__ b_ih2, const float* __restrict__ b_hh2,
    float* __restrict__ out)
{
    // ---- stage all weights into shared once ----
    __shared__ float sw[1884];
    // per-warp double-buffered broadcast: [warp][parity][32 lanes + 32 dup]
    __shared__ __align__(16) float4 hbuf[4][2][64];
    {
        int t = threadIdx.x;
        for (int i = t; i < 225; i += 128) sw[i]        = w_ih0[i];
        for (int i = t; i < 675; i += 128) sw[225 + i]  = w_hh0[i];
        for (int i = t; i <  45; i += 128) sw[900 + i]  = b_ih0[i];
        for (int i = t; i <  45; i += 128) sw[945 + i]  = b_hh0[i];
        for (int i = t; i < 450; i += 128) sw[990 + i]  = w_ih1[i];
        for (int i = t; i < 300; i += 128) sw[1440 + i] = w_hh1[i];
        for (int i = t; i <  30; i += 128) sw[1740 + i] = b_ih1[i];
        for (int i = t; i <  30; i += 128) sw[1770 + i] = b_hh1[i];
        for (int i = t; i <  60; i += 128) sw[1800 + i] = w_ih2[i];
        for (int i = t; i <  12; i += 128) sw[1860 + i] = w_hh2[i];
        for (int i = t; i <   6; i += 128) sw[1872 + i] = b_ih2[i];
        for (int i = t; i <   6; i += 128) sw[1878 + i] = b_hh2[i];
    }
    __syncthreads();
    const float* s_wih0 = sw;
    const float* s_whh0 = sw + 225;
    const float* s_bih0 = sw + 900;
    const float* s_bhh0 = sw + 945;
    const float* s_wih1 = sw + 990;
    const float* s_whh1 = sw + 1440;
    const float* s_bih1 = sw + 1740;
    const float* s_bhh1 = sw + 1770;
    const float* s_wih2 = sw + 1800;
    const float* s_whh2 = sw + 1860;
    const float* s_bih2 = sw + 1872;
    const float* s_bhh2 = sw + 1878;

    const int lane = threadIdx.x & 31;
    const int wid  = threadIdx.x >> 5;
    const int gw   = blockIdx.x * 4 + wid;
    const int b0   = gw * 4;           // batches b0 .. b0+3

    // ---- per-lane register-resident weights (unified k-loop, k = 0..24) ----
    float wr[25], wz[25], wni[15], wnh[20];
#pragma unroll
    for (int k = 0; k < 25; k++) { wr[k] = 0.f; wz[k] = 0.f; }
#pragma unroll
    for (int k = 0; k < 15; k++) wni[k] = 0.f;
#pragma unroll
    for (int k = 0; k < 20; k++) wnh[k] = 0.f;
    float br = 0.f, bz = 0.f, bni = 0.f, bnh = 0.f;

    if (lane < 15) {
        const int u = lane;
#pragma unroll
        for (int k = 0; k < 5; k++) {
            wr[k]  = s_wih0[u * 5 + k];
            wz[k]  = s_wih0[(15 + u) * 5 + k];
            wni[k] = s_wih0[(30 + u) * 5 + k];
        }
#pragma unroll
        for (int j = 0; j < 15; j++) {
            wr[5 + j]  = s_whh0[u * 15 + j];
            wz[5 + j]  = s_whh0[(15 + u) * 15 + j];
            wnh[j]     = s_whh0[(30 + u) * 15 + j];
        }
        br  = s_bih0[u] + s_bhh0[u];
        bz  = s_bih0[15 + u] + s_bhh0[15 + u];
        bni = s_bih0[30 + u];
        bnh = s_bhh0[30 + u];
    } else if (lane < 25) {
        const int u = lane - 15;
#pragma unroll
        for (int k = 0; k < 15; k++) {
            wr[k]  = s_wih1[u * 15 + k];
            wz[k]  = s_wih1[(10 + u) * 15 + k];
            wni[k] = s_wih1[(20 + u) * 15 + k];
        }
#pragma unroll
        for (int j = 0; j < 10; j++) {
            wr[15 + j]  = s_whh1[u * 10 + j];
            wz[15 + j]  = s_whh1[(10 + u) * 10 + j];
            wnh[10 + j] = s_whh1[(20 + u) * 10 + j];
        }
        br  = s_bih1[u] + s_bhh1[u];
        bz  = s_bih1[10 + u] + s_bhh1[10 + u];
        bni = s_bih1[20 + u];
        bnh = s_bhh1[20 + u];
    } else if (lane < 27) {
        const int u = lane - 25;
#pragma unroll
        for (int k = 0; k < 10; k++) {
            wr[k]  = s_wih2[u * 10 + k];
            wz[k]  = s_wih2[(2 + u) * 10 + k];
            wni[k] = s_wih2[(4 + u) * 10 + k];
        }
#pragma unroll
        for (int j = 0; j < 2; j++) {
            wr[10 + j] = s_whh2[u * 2 + j];
            wz[10 + j] = s_whh2[(2 + u) * 2 + j];
            wnh[5 + j] = s_whh2[(4 + u) * 2 + j];
        }
        br  = s_bih2[u] + s_bhh2[u];
        bz  = s_bih2[2 + u] + s_bhh2[2 + u];
        bni = s_bih2[4 + u];
        bnh = s_bhh2[4 + u];
    }

    // duplicate-packed weights (w,w) for f32x2 FMA — shared by both batch pairs
    u64 wr2[25], wz2[25], wni2[15], wnh2[20];
#pragma unroll
    for (int k = 0; k < 25; k++) { wr2[k] = pack2(wr[k], wr[k]); wz2[k] = pack2(wz[k], wz[k]); }
#pragma unroll
    for (int k = 0; k < 15; k++) wni2[k] = pack2(wni[k], wni[k]);
#pragma unroll
    for (int k = 0; k < 20; k++) wnh2[k] = pack2(wnh[k], wnh[k]);
    const u64 br2  = pack2(br, br);
    const u64 bz2  = pack2(bz, bz);
    const u64 bni2 = pack2(bni, bni);
    const u64 bnh2 = pack2(bnh, bnh);

    // read base per lane class (wrap handled by duplicate store at lane+32)
    const int base = (lane < 15) ? 27 : (lane < 25) ? 0 : (lane < 27) ? 15 : 0;

    // wavefront delay per lane; loader lanes never commit
    const int d = (lane < 15) ? 0 : (lane < 25) ? 1 : (lane < 27) ? 2 : 0x40000000;
    const bool isOut = (lane == 25) || (lane == 26);

    const int feat = (lane >= 27) ? (lane - 27) : 0;
    const float* xp = x + (size_t)b0 * IN_DIM + feat;
    const int u2 = (lane >= 25) ? (lane - 25) : 0;
    float* op = out + (size_t)b0 * 2 + u2;

    float h[4] = {0.f, 0.f, 0.f, 0.f};   // hidden state, 4 batches
    float xn[4] = {0.f, 0.f, 0.f, 0.f};  // prefetched x(t+1)
    u64 sh0 = 0, sh1 = 0;                // packed operands (b0,b1) / (b2,b3)
    if (lane >= 27) {
        sh0 = pack2(xp[0 * IN_DIM], xp[1 * IN_DIM]);             // x(0)
        sh1 = pack2(xp[2 * IN_DIM], xp[3 * IN_DIM]);
#pragma unroll
        for (int j = 0; j < 4; j++) xn[j] = xp[BATCH * IN_DIM + j * IN_DIM];  // x(1)
    }

    const float4* rd0 = &hbuf[wid][0][base];
    const float4* rd1 = &hbuf[wid][1][base];
    float4* wp0 = &hbuf[wid][0][lane];
    float4* wp1 = &hbuf[wid][1][lane];

    // initial publish of (x(0), h=0) into parity 0
    {
        float s0a, s0b, s1a, s1b;
        unpack2(sh0, s0a, s0b);
        unpack2(sh1, s1a, s1b);
        float4 v = make_float4(s0a, s0b, s1a, s1b);
        wp0[0] = v; wp0[32] = v;
    }
    __syncwarp(0xffffffffu);

    auto body = [&](int s, const float4* rd, float4* wp) {
        u64 ar0 = br2, az0 = bz2, ani0 = bni2, anh0 = bnh2;
        u64 ar1 = br2, az1 = bz2, ani1 = bni2, anh1 = bnh2;
#pragma unroll
        for (int k = 0; k < 25; k++) {
            float4 q = rd[k];                 // ld.shared.v4, immediate offset
            u64 v0 = pack2(q.x, q.y);
            u64 v1 = pack2(q.z, q.w);
            ar0 = fma2(wr2[k], v0, ar0);
            ar1 = fma2(wr2[k], v1, ar1);
            az0 = fma2(wz2[k], v0, az0);
            az1 = fma2(wz2[k], v1, az1);
            if (k < 15) { ani0 = fma2(wni2[k], v0, ani0); ani1 = fma2(wni2[k], v1, ani1); }
            if (k >= 5) { anh0 = fma2(wnh2[k - 5], v0, anh0); anh1 = fma2(wnh2[k - 5], v1, anh1); }
        }

        float arf[4], azf[4], anif[4], anhf[4], hn[4];
        unpack2(ar0, arf[0], arf[1]);    unpack2(ar1, arf[2], arf[3]);
        unpack2(az0, azf[0], azf[1]);    unpack2(az1, azf[2], azf[3]);
        unpack2(ani0, anif[0], anif[1]); unpack2(ani1, anif[2], anif[3]);
        unpack2(anh0, anhf[0], anhf[1]); unpack2(anh1, anhf[2], anhf[3]);
#pragma unroll
        for (int j = 0; j < 4; j++) {
            float r = fsig(arf[j]);
            float z = fsig(azf[j]);
            float n = ftanh_(fmaf(r, anhf[j], anif[j]));
            hn[j] = fmaf(z, h[j] - n, n);                        // (1-z)*n + z*h
        }

        bool valid = (s >= d) && (s < T_STEPS + d);
        if (valid) {
#pragma unroll
            for (int j = 0; j < 4; j++) h[j] = hn[j];
        }
        if (valid && isOut) {
            size_t o = (size_t)(s - 2) * (BATCH * 2);
#pragma unroll
            for (int j = 0; j < 4; j++) op[o + j * 2] = hn[j];
        }

        if (lane < 27) {
            sh0 = pack2(h[0], h[1]);
            sh1 = pack2(h[2], h[3]);
        } else {
            sh0 = pack2(xn[0], xn[1]);                           // becomes x(s+1)
            sh1 = pack2(xn[2], xn[3]);
            int t2 = s + 2;
            bool inb = (t2 < T_STEPS);
            size_t xo = (size_t)t2 * (BATCH * IN_DIM);
#pragma unroll
            for (int j = 0; j < 4; j++) xn[j] = inb ? xp[xo + j * IN_DIM] : 0.f;
        }

        float s0a, s0b, s1a, s1b;
        unpack2(sh0, s0a, s0b);
        unpack2(sh1, s1a, s1b);
        float4 v = make_float4(s0a, s0b, s1a, s1b);
        wp[0] = v; wp[32] = v;
        __syncwarp(0xffffffffu);
    };

    // 1026 steps, manual 2x unroll for compile-time buffer parity
    for (int s = 0; s < T_STEPS + 2; s += 2) {
        body(s,     rd0, wp1);
        body(s + 1, rd1, wp0);
    }
}

extern "C" void kernel_launch(void* const* d_in, const int* in_sizes, int n_in,
                              void* d_out, int out_size)
{
    (void)in_sizes; (void)n_in; (void)out_size;
    const float* x     = (const float*)d_in[0];
    const float* w_ih0 = (const float*)d_in[1];
    const float* w_hh0 = (const float*)d_in[2];
    const float* b_ih0 = (const float*)d_in[3];
    const float* b_hh0 = (const float*)d_in[4];
    const float* w_ih1 = (const float*)d_in[5];
    const float* w_hh1 = (const float*)d_in[6];
    const float* b_ih1 = (const float*)d_in[7];
    const float* b_hh1 = (const float*)d_in[8];
    const float* w_ih2 = (const float*)d_in[9];
    const float* w_hh2 = (const float*)d_in[10];
    const float* b_ih2 = (const float*)d_in[11];
    const float* b_hh2 = (const float*)d_in[12];

    // one warp per 4 batch elements: 1024 warps = 256 blocks x 4 warps
    gru3_fused_kernel<<<BATCH / 16, 128>>>(
        x, w_ih0, w_hh0, b_ih0, b_hh0,
        w_ih1, w_hh1, b_ih1, b_hh1,
        w_ih2, w_hh2, b_ih2, b_hh2,
        (float*)d_out);
}